// round 2
// baseline (speedup 1.0000x reference)
#include <cuda_runtime.h>
#include <math.h>

#define NQ 4
#define DIM 16
#define NB 4
#define SS 512
#define EE 512
#define NTOK (NB*SS)           // 2048
#define OUT_ELEMS (NB*SS*EE)   // 1048576

// ---------------- scratch (no device allocation allowed) ----------------
__device__ float g_q[NTOK * NQ];
__device__ float g_k[NTOK * NQ];
__device__ float g_v[NTOK * NQ];
__device__ float g_C[81];

// ---------------- complex helpers ----------------
__device__ __forceinline__ float2 cmul(float2 a, float2 b) {
    return make_float2(a.x * b.x - a.y * b.y, a.x * b.y + a.y * b.x);
}
__device__ __forceinline__ float2 cadd(float2 a, float2 b) {
    return make_float2(a.x + b.x, a.y + b.y);
}

// ============================================================
// Kernel 1: build the 81-coefficient multilinear tensor C from
// the fixed circuit unitary U (depends only on quantum_weights).
// One block, 256 threads.
// ============================================================
__global__ void setup_kernel(const float* __restrict__ qw) {
    __shared__ float2 U[DIM][DIM];   // U[d][p]: column p = U * e_p
    __shared__ float  Mre[DIM][DIM];

    int t = threadIdx.x;

    if (t < DIM) {
        int p = t;
        for (int d = 0; d < DIM; d++)
            U[d][p] = make_float2(d == p ? 1.f : 0.f, 0.f);

        for (int layer = 0; layer < 2; layer++) {
            // single-qubit rot gates
            for (int w = 0; w < NQ; w++) {
                float a = qw[(layer * NQ + w) * 3 + 0] * 0.5f;
                float b = qw[(layer * NQ + w) * 3 + 1] * 0.5f;
                float c = qw[(layer * NQ + w) * 3 + 2] * 0.5f;
                float ca = cosf(a), sa = sinf(a);
                float cb = cosf(b), sb = sinf(b);
                float cc = cosf(c), sc = sinf(c);
                // M1 = RY @ RX
                float2 m00 = make_float2( cb * ca,  sb * sa);
                float2 m01 = make_float2(-sb * ca, -cb * sa);
                float2 m10 = make_float2( sb * ca, -cb * sa);
                float2 m11 = make_float2( cb * ca, -sb * sa);
                float2 ezm = make_float2(cc, -sc);  // e^{-ic}
                float2 ezp = make_float2(cc,  sc);  // e^{+ic}
                float2 G00 = cmul(ezm, m00), G01 = cmul(ezm, m01);
                float2 G10 = cmul(ezp, m10), G11 = cmul(ezp, m11);

                int mask = 1 << (NQ - 1 - w);   // wire0 = most significant bit
                for (int i = 0; i < DIM; i++) {
                    if (i & mask) continue;
                    int j = i | mask;
                    float2 x0 = U[i][p], x1 = U[j][p];
                    U[i][p] = cadd(cmul(G00, x0), cmul(G01, x1));
                    U[j][p] = cadd(cmul(G10, x0), cmul(G11, x1));
                }
            }
            // CNOT ring: (0,1),(1,2),(2,3),(3,0)
            for (int e = 0; e < NQ; e++) {
                int cW = (e < NQ - 1) ? e : NQ - 1;
                int tW = (e < NQ - 1) ? e + 1 : 0;
                int mc = 1 << (NQ - 1 - cW);
                int mt = 1 << (NQ - 1 - tW);
                for (int i = 0; i < DIM; i++) {
                    if ((i & mc) && !(i & mt)) {
                        int j = i | mt;
                        float2 tmp = U[i][p];
                        U[i][p] = U[j][p];
                        U[j][p] = tmp;
                    }
                }
            }
        }
    }
    __syncthreads();

    // Mre[p][q] = Re( sum_d conj(U[d][p]) * z[d] * U[d][q] ), z[d] = 4 - 2*popc(d)
    {
        int p = t >> 4, q = t & 15;
        float s = 0.f;
        for (int d = 0; d < DIM; d++) {
            float z = (float)(NQ - 2 * __popc(d));
            s += z * (U[d][p].x * U[d][q].x + U[d][p].y * U[d][q].y);
        }
        Mre[p][q] = s;
    }
    __syncthreads();

    // C[m] over basis {cos, sin, 1}^4:
    //   (pb==qb): 1-term +0.5, cos-term +/-0.5 (sign = pb ? - : +)
    //   (pb!=qb): sin-term +0.5
    if (t < 81) {
        int dg[4];
        dg[0] = t / 27; dg[1] = (t / 9) % 3; dg[2] = (t / 3) % 3; dg[3] = t % 3;
        float acc = 0.f;
        for (int p = 0; p < DIM; p++) {
            for (int q = 0; q < DIM; q++) {
                float wgt = 1.f;
                #pragma unroll
                for (int w = 0; w < NQ; w++) {
                    int pb = (p >> (NQ - 1 - w)) & 1;
                    int qb = (q >> (NQ - 1 - w)) & 1;
                    int md = dg[w];
                    float f;
                    if (pb == qb)
                        f = (md == 2) ? 0.5f : ((md == 0) ? (pb ? -0.5f : 0.5f) : 0.f);
                    else
                        f = (md == 1) ? 0.5f : 0.f;
                    wgt *= f;
                }
                acc += Mre[p][q] * wgt;
            }
        }
        g_C[t] = acc;
    }
}

// ============================================================
// Kernel 2: q/k/v projections. One block per token, 256 threads.
// q = tanh(x@Wq + bq), k = tanh(x@Wk + bk), v = x@Wv + bv
// ============================================================
__global__ void qkv_kernel(const float* __restrict__ x,
                           const float* __restrict__ Wq, const float* __restrict__ bq,
                           const float* __restrict__ Wk, const float* __restrict__ bk,
                           const float* __restrict__ Wv, const float* __restrict__ bv) {
    __shared__ float sred[8 * 12];
    int tok = blockIdx.x;
    int tid = threadIdx.x;

    float p[12];
    #pragma unroll
    for (int r = 0; r < 12; r++) p[r] = 0.f;

    const float* xr = x + (size_t)tok * EE;
    for (int e = tid; e < EE; e += 256) {
        float xv = xr[e];
        float4 wq = *reinterpret_cast<const float4*>(Wq + e * 4);
        float4 wk = *reinterpret_cast<const float4*>(Wk + e * 4);
        float4 wv = *reinterpret_cast<const float4*>(Wv + e * 4);
        p[0] = fmaf(xv, wq.x, p[0]); p[1] = fmaf(xv, wq.y, p[1]);
        p[2] = fmaf(xv, wq.z, p[2]); p[3] = fmaf(xv, wq.w, p[3]);
        p[4] = fmaf(xv, wk.x, p[4]); p[5] = fmaf(xv, wk.y, p[5]);
        p[6] = fmaf(xv, wk.z, p[6]); p[7] = fmaf(xv, wk.w, p[7]);
        p[8] = fmaf(xv, wv.x, p[8]); p[9] = fmaf(xv, wv.y, p[9]);
        p[10] = fmaf(xv, wv.z, p[10]); p[11] = fmaf(xv, wv.w, p[11]);
    }
    #pragma unroll
    for (int r = 0; r < 12; r++)
        #pragma unroll
        for (int o = 16; o > 0; o >>= 1)
            p[r] += __shfl_xor_sync(0xFFFFFFFFu, p[r], o);

    int lane = tid & 31, warp = tid >> 5;
    if (lane == 0) {
        #pragma unroll
        for (int r = 0; r < 12; r++) sred[warp * 12 + r] = p[r];
    }
    __syncthreads();
    if (tid < 12) {
        float s = 0.f;
        #pragma unroll
        for (int w = 0; w < 8; w++) s += sred[w * 12 + tid];
        int wire = tid & 3;
        if (tid < 4)       g_q[tok * 4 + wire] = tanhf(s + bq[wire]);
        else if (tid < 8)  g_k[tok * 4 + wire] = tanhf(s + bk[wire]);
        else               g_v[tok * 4 + wire] = s + bv[wire];
    }
}

// exp-based tanh: |x| <= 2 here, accurate to ~1e-7 relative
__device__ __forceinline__ float ftanh(float x) {
    float e = __expf(2.f * x);
    return __fdividef(e - 1.f, e + 1.f);
}

// ============================================================
// Kernel 3: fused scores + softmax + attend + output projection.
// One block per (b,i) row, 512 threads (one per j).
// ============================================================
__global__ __launch_bounds__(512)
void main_kernel(const float* __restrict__ Wout, const float* __restrict__ bout,
                 float* __restrict__ out, float* __restrict__ attn_out, int write_attn) {
    __shared__ float Ksh[SS * NQ];
    __shared__ float Vsh[SS * NQ];
    __shared__ float Csh[81];
    __shared__ float redmax[17];
    __shared__ float red5[16 * 5 + 5];

    int blk = blockIdx.x;          // b*512 + i
    int b   = blk >> 9;
    int tid = threadIdx.x;

    if (tid < 81) Csh[tid] = g_C[tid];
    reinterpret_cast<float4*>(Ksh)[tid] =
        reinterpret_cast<const float4*>(g_k + (size_t)b * SS * NQ)[tid];
    reinterpret_cast<float4*>(Vsh)[tid] =
        reinterpret_cast<const float4*>(g_v + (size_t)b * SS * NQ)[tid];
    float4 qv = *reinterpret_cast<const float4*>(g_q + (size_t)blk * NQ);
    __syncthreads();

    int j = tid;
    float4 kv = reinterpret_cast<float4*>(Ksh)[j];

    float a0 = ftanh(qv.x + kv.x);
    float a1 = ftanh(qv.y + kv.y);
    float a2 = ftanh(qv.z + kv.z);
    float a3 = ftanh(qv.w + kv.w);

    float uu[4][3];
    uu[0][0] = __cosf(a0); uu[0][1] = __sinf(a0); uu[0][2] = 1.f;
    uu[1][0] = __cosf(a1); uu[1][1] = __sinf(a1); uu[1][2] = 1.f;
    uu[2][0] = __cosf(a2); uu[2][1] = __sinf(a2); uu[2][2] = 1.f;
    uu[3][0] = __cosf(a3); uu[3][1] = __sinf(a3); uu[3][2] = 1.f;

    // score = sum_m C[m] * prod_w u_w[m_w]  (81-term multilinear form)
    float score = 0.f;
    #pragma unroll
    for (int m0 = 0; m0 < 3; m0++) {
        float s1 = 0.f;
        #pragma unroll
        for (int m1 = 0; m1 < 3; m1++) {
            float s2 = 0.f;
            #pragma unroll
            for (int m2 = 0; m2 < 3; m2++) {
                int base = ((m0 * 3 + m1) * 3 + m2) * 3;
                float s3 = fmaf(Csh[base], uu[3][0],
                           fmaf(Csh[base + 1], uu[3][1], Csh[base + 2]));
                s2 = fmaf(s3, uu[2][m2], s2);
            }
            s1 = fmaf(s2, uu[1][m1], s1);
        }
        score = fmaf(s1, uu[0][m0], score);
    }
    score *= 0.5f;   // / sqrt(N_QUBITS)

    // ---- block max ----
    float mx = score;
    #pragma unroll
    for (int o = 16; o > 0; o >>= 1)
        mx = fmaxf(mx, __shfl_xor_sync(0xFFFFFFFFu, mx, o));
    int lane = tid & 31, warp = tid >> 5;
    if (lane == 0) redmax[warp] = mx;
    __syncthreads();
    if (tid == 0) {
        float m = redmax[0];
        #pragma unroll
        for (int w = 1; w < 16; w++) m = fmaxf(m, redmax[w]);
        redmax[16] = m;
    }
    __syncthreads();
    mx = redmax[16];

    float ej = __expf(score - mx);
    float4 vv = reinterpret_cast<float4*>(Vsh)[j];

    // ---- fused 5-way sum: {sum e, sum e*v0..v3} ----
    float vals[5] = { ej, ej * vv.x, ej * vv.y, ej * vv.z, ej * vv.w };
    #pragma unroll
    for (int r = 0; r < 5; r++)
        #pragma unroll
        for (int o = 16; o > 0; o >>= 1)
            vals[r] += __shfl_xor_sync(0xFFFFFFFFu, vals[r], o);
    if (lane == 0) {
        #pragma unroll
        for (int r = 0; r < 5; r++) red5[warp * 5 + r] = vals[r];
    }
    __syncthreads();
    if (tid < 5) {
        float s = 0.f;
        #pragma unroll
        for (int w = 0; w < 16; w++) s += red5[w * 5 + tid];
        red5[80 + tid] = s;
    }
    __syncthreads();

    float inv = __fdividef(1.f, red5[80]);
    if (write_attn)
        attn_out[(size_t)blk * SS + j] = ej * inv;

    float aw0 = red5[81] * inv;
    float aw1 = red5[82] * inv;
    float aw2 = red5[83] * inv;
    float aw3 = red5[84] * inv;

    // out[b,i,e] = sum_w attended[w] * Wout[w,e] + bout[e]   (e = tid)
    float o = bout[tid];
    o = fmaf(aw0, Wout[tid], o);
    o = fmaf(aw1, Wout[EE + tid], o);
    o = fmaf(aw2, Wout[2 * EE + tid], o);
    o = fmaf(aw3, Wout[3 * EE + tid], o);
    out[(size_t)blk * EE + tid] = o;
}

// ============================================================
extern "C" void kernel_launch(void* const* d_in, const int* in_sizes, int n_in,
                              void* d_out, int out_size) {
    const float* x    = (const float*)d_in[0];
    const float* Wq   = (const float*)d_in[1];
    const float* bq   = (const float*)d_in[2];
    const float* Wk   = (const float*)d_in[3];
    const float* bk   = (const float*)d_in[4];
    const float* Wv   = (const float*)d_in[5];
    const float* bv   = (const float*)d_in[6];
    const float* qw   = (const float*)d_in[7];
    const float* Wout = (const float*)d_in[8];
    const float* bout = (const float*)d_in[9];

    float* out = (float*)d_out;
    int write_attn = (out_size >= 2 * OUT_ELEMS) ? 1 : 0;
    float* attn = out + OUT_ELEMS;

    setup_kernel<<<1, 256>>>(qw);
    qkv_kernel<<<NTOK, 256>>>(x, Wq, bq, Wk, bk, Wv, bv);
    main_kernel<<<NTOK, 512>>>(Wout, bout, out, attn, write_attn);
}

// round 4
// speedup vs baseline: 2.0122x; 2.0122x over previous
#include <cuda_runtime.h>
#include <math.h>

#define NQ 4
#define DIM 16
#define NB 4
#define SS 512
#define EE 512
#define NTOK (NB*SS)           // 2048
#define OUT_ELEMS (NB*SS*EE)   // 1048576

// ---------------- scratch (no device allocation allowed) ----------------
__device__ float g_q[NTOK * NQ];
__device__ float g_k[NTOK * NQ];
__device__ float g_v[NTOK * NQ];
__device__ float g_C[81];

// ---------------- complex helpers ----------------
__device__ __forceinline__ float2 cmul(float2 a, float2 b) {
    return make_float2(a.x * b.x - a.y * b.y, a.x * b.y + a.y * b.x);
}
__device__ __forceinline__ float2 cadd(float2 a, float2 b) {
    return make_float2(a.x + b.x, a.y + b.y);
}

// ============================================================
// Parallel setup: build the 81-coefficient multilinear tensor C
// from the fixed circuit unitary. Runs inside qkv block 0 with
// 256 threads; ~1us of parallel work.
// ============================================================
__device__ void do_setup(const float* __restrict__ qw) {
    __shared__ float2 U[DIM][DIM];     // U[d][p]: column p = U * e_p
    __shared__ float2 G[8][4];         // per rot gate: G00,G01,G10,G11
    __shared__ float  Mre[DIM][DIM];

    int t = threadIdx.x;

    // --- all 8 rot-gate matrices in parallel (threads 0..7) ---
    if (t < 8) {
        float a = qw[t * 3 + 0] * 0.5f;
        float b = qw[t * 3 + 1] * 0.5f;
        float c = qw[t * 3 + 2] * 0.5f;
        float ca, sa, cb, sb, cc, sc;
        sincosf(a, &sa, &ca);
        sincosf(b, &sb, &cb);
        sincosf(c, &sc, &cc);
        // M1 = RY @ RX
        float2 m00 = make_float2( cb * ca,  sb * sa);
        float2 m01 = make_float2(-sb * ca, -cb * sa);
        float2 m10 = make_float2( sb * ca, -cb * sa);
        float2 m11 = make_float2( cb * ca, -sb * sa);
        float2 ezm = make_float2(cc, -sc);  // e^{-ic}
        float2 ezp = make_float2(cc,  sc);  // e^{+ic}
        G[t][0] = cmul(ezm, m00); G[t][1] = cmul(ezm, m01);
        G[t][2] = cmul(ezp, m10); G[t][3] = cmul(ezp, m11);
    }
    // --- init U = I (256 threads) ---
    {
        int d = t >> 4, p = t & 15;
        U[d][p] = make_float2(d == p ? 1.f : 0.f, 0.f);
    }
    __syncthreads();

    // --- circuit: 2 layers x (4 gate steps + 1 fused CNOT permutation) ---
    for (int layer = 0; layer < 2; layer++) {
        #pragma unroll
        for (int w = 0; w < NQ; w++) {
            if (t < 128) {
                int p = t & 15, pr = t >> 4;        // pair index 0..7
                int m = 1 << (3 - w);
                int low = m - 1;
                int i = (pr & low) | ((pr & ~low) << 1);
                int j = i | m;
                int g = layer * 4 + w;
                float2 x0 = U[i][p], x1 = U[j][p];
                U[i][p] = cadd(cmul(G[g][0], x0), cmul(G[g][1], x1));
                U[j][p] = cadd(cmul(G[g][2], x0), cmul(G[g][3], x1));
            }
            __syncthreads();
        }
        // CNOT ring (0,1)(1,2)(2,3)(3,0) composed into one permutation:
        // s_out[d] = s_in[sigma01(sigma12(sigma23(sigma30(d))))]
        {
            int d = t >> 4, p = t & 15;
            int i = d;
            i = (i & 1) ? (i ^ 8) : i;   // C(3,0): mc=1, mt=8
            i = (i & 2) ? (i ^ 1) : i;   // C(2,3): mc=2, mt=1
            i = (i & 4) ? (i ^ 2) : i;   // C(1,2): mc=4, mt=2
            i = (i & 8) ? (i ^ 4) : i;   // C(0,1): mc=8, mt=4
            float2 val = U[i][p];
            __syncthreads();
            U[d][p] = val;
            __syncthreads();
        }
    }

    // --- Mre[p][q] = Re( sum_d conj(U[d][p]) z[d] U[d][q] ), z = 4-2*popc ---
    {
        int p = t >> 4, q = t & 15;
        float s = 0.f;
        #pragma unroll
        for (int d = 0; d < DIM; d++) {
            float z = (float)(NQ - 2 * __popc(d));
            s += z * (U[d][p].x * U[d][q].x + U[d][p].y * U[d][q].y);
        }
        Mre[p][q] = s;
    }
    __syncthreads();

    // --- C tensor: per monomial m, only 16 (p,q) pairs are nonzero ---
    if (t < 81) {
        int dg[4];
        dg[0] = t / 27; dg[1] = (t / 9) % 3; dg[2] = (t / 3) % 3; dg[3] = t % 3;
        float acc = 0.f;
        #pragma unroll
        for (int c = 0; c < 16; c++) {
            int p = 0, q = 0;
            float sign = 1.f;
            #pragma unroll
            for (int w = 0; w < 4; w++) {
                int cw = (c >> w) & 1;
                int md = dg[w];
                int pb, qb;
                if (md == 1) { pb = cw; qb = cw ^ 1; }
                else         { pb = cw; qb = cw; if (md == 0 && cw) sign = -sign; }
                p |= pb << (3 - w);
                q |= qb << (3 - w);
            }
            acc += sign * Mre[p][q];
        }
        g_C[t] = acc * 0.0625f;   // (1/2)^4
    }
}

// exp-based tanh: accurate to ~1e-7 relative
__device__ __forceinline__ float ftanh(float x) {
    float e = __expf(2.f * x);
    return __fdividef(e - 1.f, e + 1.f);
}

// ============================================================
// Kernel 1: q/k/v projections, warp-per-token (8 tokens/block).
// Block 0 additionally computes the C tensor (concurrently with
// the other 255 blocks).
// ============================================================
__global__ __launch_bounds__(256)
void qkv_kernel(const float* __restrict__ x,
                const float* __restrict__ Wq, const float* __restrict__ bq,
                const float* __restrict__ Wk, const float* __restrict__ bk,
                const float* __restrict__ Wv, const float* __restrict__ bv,
                const float* __restrict__ qw) {
    if (blockIdx.x == 0) do_setup(qw);

    int warp = threadIdx.x >> 5, lane = threadIdx.x & 31;
    int tok = blockIdx.x * 8 + warp;

    float p[12];
    #pragma unroll
    for (int r = 0; r < 12; r++) p[r] = 0.f;

    const float* xr = x + (size_t)tok * EE;
    #pragma unroll 4
    for (int e = lane; e < EE; e += 32) {
        float xv = xr[e];
        float4 wq = __ldg(reinterpret_cast<const float4*>(Wq + e * 4));
        float4 wk = __ldg(reinterpret_cast<const float4*>(Wk + e * 4));
        float4 wv = __ldg(reinterpret_cast<const float4*>(Wv + e * 4));
        p[0] = fmaf(xv, wq.x, p[0]);  p[1] = fmaf(xv, wq.y, p[1]);
        p[2] = fmaf(xv, wq.z, p[2]);  p[3] = fmaf(xv, wq.w, p[3]);
        p[4] = fmaf(xv, wk.x, p[4]);  p[5] = fmaf(xv, wk.y, p[5]);
        p[6] = fmaf(xv, wk.z, p[6]);  p[7] = fmaf(xv, wk.w, p[7]);
        p[8] = fmaf(xv, wv.x, p[8]);  p[9] = fmaf(xv, wv.y, p[9]);
        p[10] = fmaf(xv, wv.z, p[10]); p[11] = fmaf(xv, wv.w, p[11]);
    }
    #pragma unroll
    for (int r = 0; r < 12; r++)
        #pragma unroll
        for (int o = 16; o > 0; o >>= 1)
            p[r] += __shfl_xor_sync(0xFFFFFFFFu, p[r], o);

    if (lane == 0) {
        g_q[tok * 4 + 0] = ftanh(p[0] + bq[0]);
        g_q[tok * 4 + 1] = ftanh(p[1] + bq[1]);
        g_q[tok * 4 + 2] = ftanh(p[2] + bq[2]);
        g_q[tok * 4 + 3] = ftanh(p[3] + bq[3]);
        g_k[tok * 4 + 0] = ftanh(p[4] + bk[0]);
        g_k[tok * 4 + 1] = ftanh(p[5] + bk[1]);
        g_k[tok * 4 + 2] = ftanh(p[6] + bk[2]);
        g_k[tok * 4 + 3] = ftanh(p[7] + bk[3]);
        g_v[tok * 4 + 0] = p[8]  + bv[0];
        g_v[tok * 4 + 1] = p[9]  + bv[1];
        g_v[tok * 4 + 2] = p[10] + bv[2];
        g_v[tok * 4 + 3] = p[11] + bv[3];
    }
}

// ============================================================
// Kernel 2: fused scores + softmax + attend + output projection.
// One block per (b,i) row, 512 threads (one per j).
// ============================================================
__global__ __launch_bounds__(512)
void main_kernel(const float* __restrict__ Wout, const float* __restrict__ bout,
                 float* __restrict__ out, float* __restrict__ attn_out) {
    __shared__ float Ksh[SS * NQ];
    __shared__ float Vsh[SS * NQ];
    __shared__ float Csh[81];
    __shared__ float redmax[17];
    __shared__ float red5[16 * 5 + 5];

    int blk = blockIdx.x;          // b*512 + i
    int b   = blk >> 9;
    int tid = threadIdx.x;

    if (tid < 81) Csh[tid] = g_C[tid];
    reinterpret_cast<float4*>(Ksh)[tid] =
        reinterpret_cast<const float4*>(g_k + (size_t)b * SS * NQ)[tid];
    reinterpret_cast<float4*>(Vsh)[tid] =
        reinterpret_cast<const float4*>(g_v + (size_t)b * SS * NQ)[tid];
    float4 qv = *reinterpret_cast<const float4*>(g_q + (size_t)blk * NQ);
    __syncthreads();

    int j = tid;
    float4 kv = reinterpret_cast<float4*>(Ksh)[j];

    float a0 = ftanh(qv.x + kv.x);
    float a1 = ftanh(qv.y + kv.y);
    float a2 = ftanh(qv.z + kv.z);
    float a3 = ftanh(qv.w + kv.w);

    float uu[4][3];
    uu[0][0] = __cosf(a0); uu[0][1] = __sinf(a0); uu[0][2] = 1.f;
    uu[1][0] = __cosf(a1); uu[1][1] = __sinf(a1); uu[1][2] = 1.f;
    uu[2][0] = __cosf(a2); uu[2][1] = __sinf(a2); uu[2][2] = 1.f;
    uu[3][0] = __cosf(a3); uu[3][1] = __sinf(a3); uu[3][2] = 1.f;

    // score = sum_m C[m] * prod_w u_w[m_w]  (81-term multilinear form)
    float score = 0.f;
    #pragma unroll
    for (int m0 = 0; m0 < 3; m0++) {
        float s1 = 0.f;
        #pragma unroll
        for (int m1 = 0; m1 < 3; m1++) {
            float s2 = 0.f;
            #pragma unroll
            for (int m2 = 0; m2 < 3; m2++) {
                int base = ((m0 * 3 + m1) * 3 + m2) * 3;
                float s3 = fmaf(Csh[base], uu[3][0],
                           fmaf(Csh[base + 1], uu[3][1], Csh[base + 2]));
                s2 = fmaf(s3, uu[2][m2], s2);
            }
            s1 = fmaf(s2, uu[1][m1], s1);
        }
        score = fmaf(s1, uu[0][m0], score);
    }
    score *= 0.5f;   // / sqrt(N_QUBITS)

    // ---- block max ----
    float mx = score;
    #pragma unroll
    for (int o = 16; o > 0; o >>= 1)
        mx = fmaxf(mx, __shfl_xor_sync(0xFFFFFFFFu, mx, o));
    int lane = tid & 31, warp = tid >> 5;
    if (lane == 0) redmax[warp] = mx;
    __syncthreads();
    if (tid == 0) {
        float m = redmax[0];
        #pragma unroll
        for (int w = 1; w < 16; w++) m = fmaxf(m, redmax[w]);
        redmax[16] = m;
    }
    __syncthreads();
    mx = redmax[16];

    float ej = __expf(score - mx);
    float4 vv = reinterpret_cast<float4*>(Vsh)[j];

    // ---- fused 5-way sum: {sum e, sum e*v0..v3} ----
    float vals[5] = { ej, ej * vv.x, ej * vv.y, ej * vv.z, ej * vv.w };
    #pragma unroll
    for (int r = 0; r < 5; r++)
        #pragma unroll
        for (int o = 16; o > 0; o >>= 1)
            vals[r] += __shfl_xor_sync(0xFFFFFFFFu, vals[r], o);
    if (lane == 0) {
        #pragma unroll
        for (int r = 0; r < 5; r++) red5[warp * 5 + r] = vals[r];
    }
    __syncthreads();
    if (tid < 5) {
        float s = 0.f;
        #pragma unroll
        for (int w = 0; w < 16; w++) s += red5[w * 5 + tid];
        red5[80 + tid] = s;
    }
    __syncthreads();

    float inv = __fdividef(1.f, red5[80]);
    attn_out[(size_t)blk * SS + j] = ej * inv;

    float aw0 = red5[81] * inv;
    float aw1 = red5[82] * inv;
    float aw2 = red5[83] * inv;
    float aw3 = red5[84] * inv;

    // out[b,i,e] = sum_w attended[w] * Wout[w,e] + bout[e]   (e = tid)
    float o = bout[tid];
    o = fmaf(aw0, Wout[tid], o);
    o = fmaf(aw1, Wout[EE + tid], o);
    o = fmaf(aw2, Wout[2 * EE + tid], o);
    o = fmaf(aw3, Wout[3 * EE + tid], o);
    out[(size_t)blk * EE + tid] = o;
}

// ============================================================
extern "C" void kernel_launch(void* const* d_in, const int* in_sizes, int n_in,
                              void* d_out, int out_size) {
    const float* x    = (const float*)d_in[0];
    const float* Wq   = (const float*)d_in[1];
    const float* bq   = (const float*)d_in[2];
    const float* Wk   = (const float*)d_in[3];
    const float* bk   = (const float*)d_in[4];
    const float* Wv   = (const float*)d_in[5];
    const float* bv   = (const float*)d_in[6];
    const float* qw   = (const float*)d_in[7];
    const float* Wout = (const float*)d_in[8];
    const float* bout = (const float*)d_in[9];

    float* out  = (float*)d_out;
    float* attn = out + OUT_ELEMS;

    qkv_kernel<<<NTOK / 8, 256>>>(x, Wq, bq, Wk, bk, Wv, bv, qw);
    main_kernel<<<NTOK, 512>>>(Wout, bout, out, attn);
}

// round 9
// speedup vs baseline: 2.1309x; 1.0590x over previous
#include <cuda_runtime.h>
#include <math.h>

#define NQ 4
#define DIM 16
#define NB 4
#define SS 512
#define EE 512
#define NTOK (NB*SS)           // 2048
#define OUT_ELEMS (NB*SS*EE)   // 1048576

// ---------------- scratch (no device allocation allowed) ----------------
__device__ float4 g_q4[NTOK];
__device__ float4 g_k4[NTOK];
__device__ float4 g_v4[NTOK];
__device__ float4 g_C4[27];    // padded triples, includes 1/sqrt(NQ) scale

// ---------------- complex helpers ----------------
__device__ __forceinline__ float2 cmul(float2 a, float2 b) {
    return make_float2(a.x * b.x - a.y * b.y, a.x * b.y + a.y * b.x);
}
__device__ __forceinline__ float2 cadd(float2 a, float2 b) {
    return make_float2(a.x + b.x, a.y + b.y);
}

// ============================================================
// Parallel setup: build the 81-coefficient multilinear tensor C
// from the fixed circuit unitary. Runs inside qkv block 0 with
// 256 threads; ~1us of parallel work, hidden behind other blocks.
// ============================================================
__device__ void do_setup(const float* __restrict__ qw) {
    __shared__ float2 U[DIM][DIM];     // U[d][p]: column p = U * e_p
    __shared__ float2 G[8][4];         // per rot gate: G00,G01,G10,G11
    __shared__ float  Mre[DIM][DIM];
    __shared__ float  Ctmp[81];

    int t = threadIdx.x;

    // --- all 8 rot-gate matrices in parallel (threads 0..7) ---
    if (t < 8) {
        float a = qw[t * 3 + 0] * 0.5f;
        float b = qw[t * 3 + 1] * 0.5f;
        float c = qw[t * 3 + 2] * 0.5f;
        float ca, sa, cb, sb, cc, sc;
        sincosf(a, &sa, &ca);
        sincosf(b, &sb, &cb);
        sincosf(c, &sc, &cc);
        // M1 = RY @ RX
        float2 m00 = make_float2( cb * ca,  sb * sa);
        float2 m01 = make_float2(-sb * ca, -cb * sa);
        float2 m10 = make_float2( sb * ca, -cb * sa);
        float2 m11 = make_float2( cb * ca, -sb * sa);
        float2 ezm = make_float2(cc, -sc);  // e^{-ic}
        float2 ezp = make_float2(cc,  sc);  // e^{+ic}
        G[t][0] = cmul(ezm, m00); G[t][1] = cmul(ezm, m01);
        G[t][2] = cmul(ezp, m10); G[t][3] = cmul(ezp, m11);
    }
    // --- init U = I (256 threads) ---
    {
        int d = t >> 4, p = t & 15;
        U[d][p] = make_float2(d == p ? 1.f : 0.f, 0.f);
    }
    __syncthreads();

    // --- circuit: 2 layers x (4 gate steps + 1 fused CNOT permutation) ---
    for (int layer = 0; layer < 2; layer++) {
        #pragma unroll
        for (int w = 0; w < NQ; w++) {
            if (t < 128) {
                int p = t & 15, pr = t >> 4;        // pair index 0..7
                int m = 1 << (3 - w);
                int low = m - 1;
                int i = (pr & low) | ((pr & ~low) << 1);
                int j = i | m;
                int g = layer * 4 + w;
                float2 x0 = U[i][p], x1 = U[j][p];
                U[i][p] = cadd(cmul(G[g][0], x0), cmul(G[g][1], x1));
                U[j][p] = cadd(cmul(G[g][2], x0), cmul(G[g][3], x1));
            }
            __syncthreads();
        }
        // CNOT ring (0,1)(1,2)(2,3)(3,0) composed into one permutation
        {
            int d = t >> 4, p = t & 15;
            int i = d;
            i = (i & 1) ? (i ^ 8) : i;   // C(3,0)
            i = (i & 2) ? (i ^ 1) : i;   // C(2,3)
            i = (i & 4) ? (i ^ 2) : i;   // C(1,2)
            i = (i & 8) ? (i ^ 4) : i;   // C(0,1)
            float2 val = U[i][p];
            __syncthreads();
            U[d][p] = val;
            __syncthreads();
        }
    }

    // --- Mre[p][q] = Re( sum_d conj(U[d][p]) z[d] U[d][q] ) ---
    {
        int p = t >> 4, q = t & 15;
        float s = 0.f;
        #pragma unroll
        for (int d = 0; d < DIM; d++) {
            float z = (float)(NQ - 2 * __popc(d));
            s += z * (U[d][p].x * U[d][q].x + U[d][p].y * U[d][q].y);
        }
        Mre[p][q] = s;
    }
    __syncthreads();

    // --- C tensor: per monomial m, only 16 (p,q) pairs are nonzero ---
    if (t < 81) {
        int dg[4];
        dg[0] = t / 27; dg[1] = (t / 9) % 3; dg[2] = (t / 3) % 3; dg[3] = t % 3;
        float acc = 0.f;
        #pragma unroll
        for (int c = 0; c < 16; c++) {
            int p = 0, q = 0;
            float sign = 1.f;
            #pragma unroll
            for (int w = 0; w < 4; w++) {
                int cw = (c >> w) & 1;
                int md = dg[w];
                int pb, qb;
                if (md == 1) { pb = cw; qb = cw ^ 1; }
                else         { pb = cw; qb = cw; if (md == 0 && cw) sign = -sign; }
                p |= pb << (3 - w);
                q |= qb << (3 - w);
            }
            acc += sign * Mre[p][q];
        }
        // (1/2)^4 per-wire half-angle factors * 0.5 softmax scale (1/sqrt(NQ))
        Ctmp[t] = acc * 0.03125f;
    }
    __syncthreads();
    if (t < 27)
        g_C4[t] = make_float4(Ctmp[3 * t], Ctmp[3 * t + 1], Ctmp[3 * t + 2], 0.f);
}

// exp-based tanh: accurate to ~1e-7 relative
__device__ __forceinline__ float ftanh(float x) {
    float e = __expf(2.f * x);
    return __fdividef(e - 1.f, e + 1.f);
}

// ============================================================
// Kernel 1: q/k/v projections, warp-per-token (8 tokens/block).
// Block 0 additionally computes the C tensor.
// ============================================================
__global__ __launch_bounds__(256)
void qkv_kernel(const float* __restrict__ x,
                const float* __restrict__ Wq, const float* __restrict__ bq,
                const float* __restrict__ Wk, const float* __restrict__ bk,
                const float* __restrict__ Wv, const float* __restrict__ bv,
                const float* __restrict__ qw) {
    if (blockIdx.x == 0) do_setup(qw);

    int warp = threadIdx.x >> 5, lane = threadIdx.x & 31;
    int tok = blockIdx.x * 8 + warp;

    float p[12];
    #pragma unroll
    for (int r = 0; r < 12; r++) p[r] = 0.f;

    const float* xr = x + (size_t)tok * EE;
    #pragma unroll 4
    for (int e = lane; e < EE; e += 32) {
        float xv = xr[e];
        float4 wq = __ldg(reinterpret_cast<const float4*>(Wq + e * 4));
        float4 wk = __ldg(reinterpret_cast<const float4*>(Wk + e * 4));
        float4 wv = __ldg(reinterpret_cast<const float4*>(Wv + e * 4));
        p[0] = fmaf(xv, wq.x, p[0]);  p[1] = fmaf(xv, wq.y, p[1]);
        p[2] = fmaf(xv, wq.z, p[2]);  p[3] = fmaf(xv, wq.w, p[3]);
        p[4] = fmaf(xv, wk.x, p[4]);  p[5] = fmaf(xv, wk.y, p[5]);
        p[6] = fmaf(xv, wk.z, p[6]);  p[7] = fmaf(xv, wk.w, p[7]);
        p[8] = fmaf(xv, wv.x, p[8]);  p[9] = fmaf(xv, wv.y, p[9]);
        p[10] = fmaf(xv, wv.z, p[10]); p[11] = fmaf(xv, wv.w, p[11]);
    }
    #pragma unroll
    for (int r = 0; r < 12; r++)
        #pragma unroll
        for (int o = 16; o > 0; o >>= 1)
            p[r] += __shfl_xor_sync(0xFFFFFFFFu, p[r], o);

    if (lane == 0) {
        float* gq = (float*)g_q4;
        float* gk = (float*)g_k4;
        float* gv = (float*)g_v4;
        gq[tok * 4 + 0] = ftanh(p[0] + bq[0]);
        gq[tok * 4 + 1] = ftanh(p[1] + bq[1]);
        gq[tok * 4 + 2] = ftanh(p[2] + bq[2]);
        gq[tok * 4 + 3] = ftanh(p[3] + bq[3]);
        gk[tok * 4 + 0] = ftanh(p[4] + bk[0]);
        gk[tok * 4 + 1] = ftanh(p[5] + bk[1]);
        gk[tok * 4 + 2] = ftanh(p[6] + bk[2]);
        gk[tok * 4 + 3] = ftanh(p[7] + bk[3]);
        gv[tok * 4 + 0] = p[8]  + bv[0];
        gv[tok * 4 + 1] = p[9]  + bv[1];
        gv[tok * 4 + 2] = p[10] + bv[2];
        gv[tok * 4 + 3] = p[11] + bv[3];
    }
}

// ============================================================
// Kernel 2: warp-per-row fused scores + softmax + attend + proj.
// 512 blocks x 128 threads; each warp owns one (b,i) row.
// No max-subtraction: score is bounded in [-2,2] analytically.
// ============================================================
__global__ void __launch_bounds__(128, 8)
main_kernel(const float* __restrict__ Wout, const float* __restrict__ bout,
            float* __restrict__ out, float* __restrict__ attn_out) {
    __shared__ float4 Ksh[SS];
    __shared__ float4 Vsh[SS];
    __shared__ float4 C4[27];
    __shared__ float  WoSh[4 * EE];
    __shared__ float  boSh[EE];

    int tid = threadIdx.x, lane = tid & 31, warp = tid >> 5;
    int row = blockIdx.x * 4 + warp;      // (b*512 + i)
    int b   = blockIdx.x >> 7;

    for (int i = tid; i < SS; i += 128) {
        Ksh[i] = g_k4[b * SS + i];
        Vsh[i] = g_v4[b * SS + i];
    }
    for (int i = tid; i < 4 * EE; i += 128) WoSh[i] = Wout[i];
    for (int i = tid; i < EE; i += 128)     boSh[i] = bout[i];
    if (tid < 27) C4[tid] = g_C4[tid];
    __syncthreads();

    float4 qv = g_q4[row];

    float ej[16];
    float se = 0.f, sv0 = 0.f, sv1 = 0.f, sv2 = 0.f, sv3 = 0.f;

    #pragma unroll
    for (int it = 0; it < 16; it++) {
        int j = it * 32 + lane;
        float4 kv = Ksh[j];

        float a0 = ftanh(qv.x + kv.x);
        float a1 = ftanh(qv.y + kv.y);
        float a2 = ftanh(qv.z + kv.z);
        float a3 = ftanh(qv.w + kv.w);

        float c0, s0, c1, s1, c2, s2, c3, s3;
        __sincosf(a0, &s0, &c0);
        __sincosf(a1, &s1, &c1);
        __sincosf(a2, &s2, &c2);
        __sincosf(a3, &s3, &c3);
        float u0[2] = {c0, s0}, u1[2] = {c1, s1}, u2[2] = {c2, s2};

        // score = sum_m C[m] * prod_w u_w[m_w], scale pre-folded into C
        float score = 0.f;
        #pragma unroll
        for (int m0 = 0; m0 < 3; m0++) {
            float t1 = 0.f;
            #pragma unroll
            for (int m1 = 0; m1 < 3; m1++) {
                float t2 = 0.f;
                #pragma unroll
                for (int m2 = 0; m2 < 3; m2++) {
                    float4 c = C4[(m0 * 3 + m1) * 3 + m2];
                    float t3 = fmaf(c.x, c3, fmaf(c.y, s3, c.z));
                    t2 = (m2 == 2) ? (t2 + t3) : fmaf(t3, u2[m2], t2);
                }
                t1 = (m1 == 2) ? (t1 + t2) : fmaf(t2, u1[m1], t1);
            }
            score = (m0 == 2) ? (score + t1) : fmaf(t1, u0[m0], score);
        }

        float e = __expf(score);
        ej[it] = e;
        float4 vv = Vsh[j];
        se  += e;
        sv0 = fmaf(e, vv.x, sv0);
        sv1 = fmaf(e, vv.y, sv1);
        sv2 = fmaf(e, vv.z, sv2);
        sv3 = fmaf(e, vv.w, sv3);
    }

    // single warp reduction of 5 values
    #pragma unroll
    for (int o = 16; o > 0; o >>= 1) {
        se  += __shfl_xor_sync(0xFFFFFFFFu, se,  o);
        sv0 += __shfl_xor_sync(0xFFFFFFFFu, sv0, o);
        sv1 += __shfl_xor_sync(0xFFFFFFFFu, sv1, o);
        sv2 += __shfl_xor_sync(0xFFFFFFFFu, sv2, o);
        sv3 += __shfl_xor_sync(0xFFFFFFFFu, sv3, o);
    }
    float inv = __fdividef(1.f, se);

    float* arow = attn_out + (size_t)row * SS;
    #pragma unroll
    for (int it = 0; it < 16; it++)
        arow[it * 32 + lane] = ej[it] * inv;

    float aw0 = sv0 * inv, aw1 = sv1 * inv, aw2 = sv2 * inv, aw3 = sv3 * inv;

    float* orow = out + (size_t)row * EE;
    #pragma unroll
    for (int it = 0; it < 16; it++) {
        int e = it * 32 + lane;
        float o = boSh[e];
        o = fmaf(aw0, WoSh[e], o);
        o = fmaf(aw1, WoSh[EE + e], o);
        o = fmaf(aw2, WoSh[2 * EE + e], o);
        o = fmaf(aw3, WoSh[3 * EE + e], o);
        orow[e] = o;
    }
}

// ============================================================
extern "C" void kernel_launch(void* const* d_in, const int* in_sizes, int n_in,
                              void* d_out, int out_size) {
    const float* x    = (const float*)d_in[0];
    const float* Wq   = (const float*)d_in[1];
    const float* bq   = (const float*)d_in[2];
    const float* Wk   = (const float*)d_in[3];
    const float* bk   = (const float*)d_in[4];
    const float* Wv   = (const float*)d_in[5];
    const float* bv   = (const float*)d_in[6];
    const float* qw   = (const float*)d_in[7];
    const float* Wout = (const float*)d_in[8];
    const float* bout = (const float*)d_in[9];

    float* out  = (float*)d_out;
    float* attn = out + OUT_ELEMS;

    qkv_kernel<<<NTOK / 8, 256>>>(x, Wq, bq, Wk, bk, Wv, bv, qw);
    main_kernel<<<NTOK / 4, 128>>>(Wout, bout, out, attn);
}